// round 6
// baseline (speedup 1.0000x reference)
#include <cuda_runtime.h>
#include <math.h>

#define Bsz 4
#define Hh  8
#define Ll  2048
#define Ss  2048
#define Ee  64
#define BH  (Bsz*Hh)
#define EPSF 1e-6f
#define SCALE 0.125f   /* 1/sqrt(64) */

// ---------------- scratch (static __device__, no allocation) ----------------
__device__ float g_qt[(size_t)BH * Ll * Ee];          // 16 MB, [B,H,L,E]
__device__ float g_kt[(size_t)BH * Ss * Ee];          // 16 MB, [B,H,S,E]
__device__ float g_scores[(size_t)BH * Ll * Ss];      // 512 MB, [B,H,L,S]
__device__ float g_rowsum[BH * Ll];
__device__ float g_rowsumsq[BH * Ll];
__device__ float g_rowmax[BH * Ll];

__device__ __forceinline__ void atomicMaxFloat(float* addr, float val) {
    int* ai = (int*)addr;
    int old = *ai;
    while (__int_as_float(old) < val) {
        int assumed = old;
        old = atomicCAS(ai, assumed, __float_as_int(val));
        if (old == assumed) break;
    }
}

// ---------------- K0: reset row stats (every launch, graph-replay safe) ----
__global__ __launch_bounds__(256) void init_stats_kernel() {
    int i = blockIdx.x * blockDim.x + threadIdx.x;
    if (i < BH * Ll) {
        g_rowsum[i]   = 0.f;
        g_rowsumsq[i] = 0.f;
        g_rowmax[i]   = -INFINITY;
    }
}

// ---------------- K1: std over H (axis=-2 of [B,L,H,E]!) + tanh transform --
// One thread per (b,l,e). Reads the 8 head values (stride Ee floats),
// computes unbiased std over H, writes transformed values to [B,H,L,E].
// grid covers 2 * B*L*E threads (queries then keys).
__global__ __launch_bounds__(256) void transform_kernel(
    const float* __restrict__ qg, const float* __restrict__ kg,
    const float* __restrict__ dw, const float* __restrict__ dp)
{
    const int NPT = Bsz * Ll * Ee;                   // per-tensor thread count
    int gid = blockIdx.x * blockDim.x + threadIdx.x;
    int which = (gid >= NPT) ? 1 : 0;
    int id = gid - which * NPT;
    const float* x  = which ? kg   : qg;
    float*       xt = which ? g_kt : g_qt;

    int e  = id & 63;
    int bl = id >> 6;                                // b*Ll + l
    int b  = bl >> 11, l = bl & 2047;

    const float* base = x + ((size_t)bl * Hh) * Ee + e;   // [b,l,h,e], h stride = Ee
    float v[Hh];
    float s1 = 0.f;
    #pragma unroll
    for (int h = 0; h < Hh; h++) { v[h] = base[h * Ee]; s1 += v[h]; }
    float mean = s1 * (1.f / Hh);
    float s2 = 0.f;
    #pragma unroll
    for (int h = 0; h < Hh; h++) { float d = v[h] - mean; s2 += d * d; }
    float stdv = sqrtf(s2 * (1.f / (Hh - 1)));
    float sc = (1.f / (stdv + EPSF)) * dw[0];
    float p  = dp[0];

    // write [B,H,L,E]: ((b*Hh + h)*Ll + l)*Ee + e
    size_t obase = (((size_t)b * Hh) * Ll + l) * Ee + e;
    #pragma unroll
    for (int h = 0; h < Hh; h++)
        xt[obase + (size_t)h * Ll * Ee] = tanhf(v[h] * sc) * p;
}

// ---------------- K2: scores = qt @ kt^T, + row stats ----------------------
// grid (S/64, L/64, BH), 256 threads, 4x4 microtile per thread.
__global__ __launch_bounds__(256) void qk_kernel()
{
    int bh = blockIdx.z;
    int l0 = blockIdx.y << 6;
    int s0 = blockIdx.x << 6;

    __shared__ float Qs[64][65];
    __shared__ float Ks[64][65];

    int t = threadIdx.x;
    int e = t & 63, r0 = t >> 6;
    const float* qb = g_qt + ((size_t)bh * Ll + l0) * Ee;
    const float* kb = g_kt + ((size_t)bh * Ss + s0) * Ee;
    #pragma unroll
    for (int i = 0; i < 16; i++) {
        int r = r0 + i * 4;
        Qs[r][e] = qb[r * Ee + e];
        Ks[r][e] = kb[r * Ee + e];
    }
    __syncthreads();

    int tx = t & 15, ty = t >> 4;
    float acc[4][4] = {};
    #pragma unroll 8
    for (int k = 0; k < 64; k++) {
        float a[4], bb[4];
        #pragma unroll
        for (int i = 0; i < 4; i++) a[i]  = Qs[ty * 4 + i][k];
        #pragma unroll
        for (int j = 0; j < 4; j++) bb[j] = Ks[tx * 4 + j][k];
        #pragma unroll
        for (int i = 0; i < 4; i++)
            #pragma unroll
            for (int j = 0; j < 4; j++)
                acc[i][j] += a[i] * bb[j];
    }

    float* srow = g_scores + ((size_t)bh * Ll + l0) * Ss + s0;
    #pragma unroll
    for (int i = 0; i < 4; i++) {
        int r = ty * 4 + i;
        *reinterpret_cast<float4*>(&srow[(size_t)r * Ss + tx * 4]) =
            make_float4(acc[i][0], acc[i][1], acc[i][2], acc[i][3]);

        float rs = (acc[i][0] + acc[i][1]) + (acc[i][2] + acc[i][3]);
        float rq = (acc[i][0]*acc[i][0] + acc[i][1]*acc[i][1]) +
                   (acc[i][2]*acc[i][2] + acc[i][3]*acc[i][3]);
        float rm = fmaxf(fmaxf(acc[i][0], acc[i][1]), fmaxf(acc[i][2], acc[i][3]));
        // reduce across the 16 tx-lanes sharing this row (stays inside 16-lane half)
        #pragma unroll
        for (int off = 8; off; off >>= 1) {
            rs += __shfl_xor_sync(0xffffffffu, rs, off);
            rq += __shfl_xor_sync(0xffffffffu, rq, off);
            rm  = fmaxf(rm, __shfl_xor_sync(0xffffffffu, rm, off));
        }
        if (tx == 0) {
            int row = bh * Ll + l0 + r;
            atomicAdd(&g_rowsum[row],   rs);
            atomicAdd(&g_rowsumsq[row], rq);
            atomicMaxFloat(&g_rowmax[row], rm);
        }
    }
}

// ---------------- K3: tau + softmax + A@V ----------------------------------
// grid (L/64, BH), 256 threads. Streams score tiles from scratch, exp, AV GEMM.
__global__ __launch_bounds__(256) void av_kernel(
    const float* __restrict__ vglob, float* __restrict__ out)
{
    int bh = blockIdx.y;
    int b = bh / Hh, h = bh % Hh;
    int l0 = blockIdx.x << 6;

    __shared__ float Ps[64][64];
    __shared__ float Vs[64][64];
    __shared__ float cs[64], ms[64];

    int t = threadIdx.x;
    if (t < 64) {
        int row = bh * Ll + l0 + t;
        float s1 = g_rowsum[row], s2 = g_rowsumsq[row];
        float mean = s1 / (float)Ss;
        float var  = fmaxf((s2 - s1 * mean) / (float)(Ss - 1), 0.f);
        cs[t] = SCALE / sqrtf(var + EPSF);   // c = scale / tau  (>0)
        ms[t] = g_rowmax[row];
    }
    __syncthreads();

    int tx = t & 15, ty = t >> 4;
    int e = t & 63,  k0 = t >> 6;
    float o[4][4] = {};
    float den[4] = {};
    float cr[4], mr[4];
    #pragma unroll
    for (int i = 0; i < 4; i++) { cr[i] = cs[ty * 4 + i]; mr[i] = ms[ty * 4 + i]; }

    const float* srow = g_scores + ((size_t)bh * Ll + l0) * Ss;
    const float* vb   = vglob + ((size_t)b * Ss * Hh + h) * Ee;

    for (int st = 0; st < Ss / 64; st++) {
        int s0 = st << 6;
        // load V tile [64 keys][64 dims]
        #pragma unroll
        for (int i = 0; i < 16; i++) {
            int k = k0 + i * 4;
            Vs[k][e] = vb[(size_t)(s0 + k) * (Hh * Ee) + e];
        }
        // read score tile, exponentiate (stable: c*(s - rowmax)), accumulate denom
        #pragma unroll
        for (int i = 0; i < 4; i++) {
            int r = ty * 4 + i;
            float4 sv = *reinterpret_cast<const float4*>(&srow[(size_t)r * Ss + s0 + tx * 4]);
            float p0 = __expf(cr[i] * (sv.x - mr[i]));
            float p1 = __expf(cr[i] * (sv.y - mr[i]));
            float p2 = __expf(cr[i] * (sv.z - mr[i]));
            float p3 = __expf(cr[i] * (sv.w - mr[i]));
            den[i] += (p0 + p1) + (p2 + p3);
            *reinterpret_cast<float4*>(&Ps[r][tx * 4]) = make_float4(p0, p1, p2, p3);
        }
        __syncthreads();
        // O += P @ V
        #pragma unroll 8
        for (int k = 0; k < 64; k++) {
            float4 bv = *reinterpret_cast<const float4*>(&Vs[k][tx * 4]);
            #pragma unroll
            for (int i = 0; i < 4; i++) {
                float a = Ps[ty * 4 + i][k];
                o[i][0] += a * bv.x; o[i][1] += a * bv.y;
                o[i][2] += a * bv.z; o[i][3] += a * bv.w;
            }
        }
        __syncthreads();
    }

    // reduce denom across the 16 tx-lanes sharing each row
    #pragma unroll
    for (int i = 0; i < 4; i++)
        #pragma unroll
        for (int off = 8; off; off >>= 1)
            den[i] += __shfl_xor_sync(0xffffffffu, den[i], off);

    #pragma unroll
    for (int i = 0; i < 4; i++) {
        int l = l0 + ty * 4 + i;
        float invd = 1.f / den[i];
        *reinterpret_cast<float4*>(&out[(((size_t)b * Ll + l) * Hh + h) * Ee + tx * 4]) =
            make_float4(o[i][0] * invd, o[i][1] * invd, o[i][2] * invd, o[i][3] * invd);
    }
}

// ---------------- launch ----------------------------------------------------
extern "C" void kernel_launch(void* const* d_in, const int* in_sizes, int n_in,
                              void* d_out, int out_size)
{
    const float* q  = (const float*)d_in[0];
    const float* k  = (const float*)d_in[1];
    const float* v  = (const float*)d_in[2];
    // d_in[3] attn_mask: unused (mask_flag=False in reference)
    const float* dw = (const float*)d_in[4];
    const float* dp = (const float*)d_in[5];
    float* out = (float*)d_out;

    init_stats_kernel<<<(BH * Ll + 255) / 256, 256>>>();
    const int NPT = Bsz * Ll * Ee;
    transform_kernel<<<(2 * NPT + 255) / 256, 256>>>(q, k, dw, dp);
    dim3 g2(Ss / 64, Ll / 64, BH);
    qk_kernel<<<g2, 256>>>();
    dim3 g3(Ll / 64, BH);
    av_kernel<<<g3, 256>>>(v, out);
}

// round 12
// speedup vs baseline: 4.7485x; 4.7485x over previous
#include <cuda_runtime.h>
#include <cuda_fp16.h>
#include <math.h>
#include <stdint.h>

#define Bsz 4
#define Hh  8
#define Ll  2048
#define Ss  2048
#define Ee  64
#define BH  32
#define EPSF 1e-6f
#define SCALE 0.125f   /* 1/sqrt(64) */

// ---------------- scratch (static __device__, no allocation) ----------------
__device__ __half g_qt[(size_t)BH * Ll * Ee];   // [bh][l][e]
__device__ __half g_kt[(size_t)BH * Ss * Ee];   // [bh][s][e]
__device__ __half g_vt[(size_t)BH * Ee * Ss];   // [bh][e][s]  (V transposed)

// ---------------- PTX helpers (base-target instructions only) ---------------
__device__ __forceinline__ uint32_t smem_u32(const void* p) {
    uint32_t a;
    asm("{ .reg .u64 t; cvta.to.shared.u64 t, %1; cvt.u32.u64 %0, t; }" : "=r"(a) : "l"(p));
    return a;
}

#define LDMX4(r0, r1, r2, r3, addr) \
    asm volatile("ldmatrix.sync.aligned.m8n8.x4.shared.b16 {%0,%1,%2,%3}, [%4];" \
        : "=r"(r0), "=r"(r1), "=r"(r2), "=r"(r3) : "r"(addr))

__device__ __forceinline__ void mma16816(float* d, const uint32_t* a,
                                         uint32_t b0, uint32_t b1) {
    asm volatile("mma.sync.aligned.m16n8k16.row.col.f32.f16.f16.f32 "
        "{%0,%1,%2,%3},{%4,%5,%6,%7},{%8,%9},{%0,%1,%2,%3};"
        : "+f"(d[0]), "+f"(d[1]), "+f"(d[2]), "+f"(d[3])
        : "r"(a[0]), "r"(a[1]), "r"(a[2]), "r"(a[3]), "r"(b0), "r"(b1));
}

// ---------------- K1: std over H (axis=-2 of [B,L,H,E]) + tanh, fp16 out ---
__global__ __launch_bounds__(256) void transform_kernel(
    const float* __restrict__ qg, const float* __restrict__ kg,
    const float* __restrict__ dw, const float* __restrict__ dp)
{
    const int NPT = Bsz * Ll * Ee;
    int gid = blockIdx.x * blockDim.x + threadIdx.x;
    int which = (gid >= NPT) ? 1 : 0;
    int id = gid - which * NPT;
    const float* x  = which ? kg   : qg;
    __half*      xt = which ? g_kt : g_qt;

    int e  = id & 63;
    int bl = id >> 6;
    int b  = bl >> 11, l = bl & 2047;

    const float* base = x + ((size_t)bl * Hh) * Ee + e;
    float v[Hh];
    float s1 = 0.f;
    #pragma unroll
    for (int h = 0; h < Hh; h++) { v[h] = base[h * Ee]; s1 += v[h]; }
    float mean = s1 * (1.f / Hh);
    float s2 = 0.f;
    #pragma unroll
    for (int h = 0; h < Hh; h++) { float d = v[h] - mean; s2 += d * d; }
    float stdv = sqrtf(s2 * (1.f / (Hh - 1)));
    float sc = (1.f / (stdv + EPSF)) * dw[0];
    float p  = dp[0];

    size_t obase = (((size_t)b * Hh) * Ll + l) * Ee + e;
    #pragma unroll
    for (int h = 0; h < Hh; h++)
        xt[obase + (size_t)h * Ll * Ee] = __float2half(tanhf(v[h] * sc) * p);
}

// ---------------- K1b: V transpose to [bh][e][s], fp16 ----------------------
__global__ __launch_bounds__(256) void vtrans_kernel(const float* __restrict__ v)
{
    __shared__ float tile[64][65];
    int bh = blockIdx.y;
    int b = bh >> 3, h = bh & 7;
    int s0 = blockIdx.x << 6;
    int t = threadIdx.x;
    int e = t & 63, sr = t >> 6;
    const float* vb = v + ((size_t)b * Ss * Hh + h) * Ee;
    #pragma unroll
    for (int i = 0; i < 16; i++) {
        int s = sr + i * 4;
        tile[s][e] = vb[(size_t)(s0 + s) * (Hh * Ee) + e];
    }
    __syncthreads();
    int sp = t & 63, er = t >> 6;
    __half* ob = g_vt + (size_t)bh * Ee * Ss;
    #pragma unroll
    for (int i = 0; i < 16; i++) {
        int e2 = er + i * 4;
        ob[(size_t)e2 * Ss + s0 + sp] = __float2half(tile[sp][e2]);
    }
}

// ---------------- K2: fused two-pass flash attention (mma.sync HMMA) --------
// grid (Ll/128, BH), 256 thr = 8 warps. Each warp owns 16 L-rows.
// Phase A: QK over all 16 S-tiles -> row sum/sumsq/max -> c = scale/tau, m.
// Phase B: recompute QK, exp in regs, pack fp16 A-frags, PV mma, normalize.
__global__ __launch_bounds__(256) void attn_kernel(float* __restrict__ out)
{
    __shared__ __align__(16) __half Ksm[128 * 72];   // 18432 B, pad 8 halves/row
    __shared__ __align__(16) __half Vsm[64 * 136];   // 17408 B, pad 8 halves/row

    int t = threadIdx.x, lane = t & 31, wid = t >> 5;
    int bh = blockIdx.y, l0 = blockIdx.x << 7;
    int b = bh >> 3, h = bh & 7;
    int wrow = wid * 16;
    int g = lane >> 2, tig = lane & 3;

    uint32_t ksb = smem_u32(Ksm), vsb = smem_u32(Vsm);

    // ---- stage Q tile into Ksm, load resident A fragments ----
    {
        const uint4* qsrc = (const uint4*)(g_qt + ((size_t)bh * Ll + l0) * Ee);
        #pragma unroll
        for (int i = 0; i < 4; i++) {
            int idx = t + i * 256;
            *(uint4*)&Ksm[(idx >> 3) * 72 + (idx & 7) * 8] = qsrc[idx];
        }
    }
    __syncthreads();
    uint32_t aq[4][4];
    {
        int r  = wrow + ((lane >> 3) & 1) * 8 + (lane & 7);
        int cb = ((lane >> 4) & 1) * 8;
        #pragma unroll
        for (int kk = 0; kk < 4; kk++) {
            uint32_t addr = ksb + (uint32_t)(r * 72 + kk * 16 + cb) * 2;
            LDMX4(aq[kk][0], aq[kk][1], aq[kk][2], aq[kk][3], addr);
        }
    }
    __syncthreads();

    const uint4* kbase = (const uint4*)(g_kt + (size_t)bh * Ss * Ee);
    const uint4* vbase = (const uint4*)(g_vt + (size_t)bh * Ee * Ss);

    // ---- phase A: row statistics ----
    float sum_lo = 0.f, sum_hi = 0.f, sq_lo = 0.f, sq_hi = 0.f;
    float mx_lo = -INFINITY, mx_hi = -INFINITY;

    for (int st = 0; st < 16; st++) {
        const uint4* ksrc = kbase + st * 1024;
        #pragma unroll
        for (int i = 0; i < 4; i++) {
            int idx = t + i * 256;
            *(uint4*)&Ksm[(idx >> 3) * 72 + (idx & 7) * 8] = ksrc[idx];
        }
        __syncthreads();
        #pragma unroll
        for (int j = 0; j < 16; j++) {
            float acc[4] = {0.f, 0.f, 0.f, 0.f};
            uint32_t addr = ksb + (uint32_t)((j * 8 + (lane & 7)) * 72 + (lane >> 3) * 8) * 2;
            uint32_t b0, b1, b2, b3, b4, b5, b6, b7;
            LDMX4(b0, b1, b2, b3, addr);
            LDMX4(b4, b5, b6, b7, addr + 64);
            mma16816(acc, aq[0], b0, b1);
            mma16816(acc, aq[1], b2, b3);
            mma16816(acc, aq[2], b4, b5);
            mma16816(acc, aq[3], b6, b7);
            sum_lo += acc[0] + acc[1];
            sq_lo  += acc[0] * acc[0] + acc[1] * acc[1];
            mx_lo   = fmaxf(mx_lo, fmaxf(acc[0], acc[1]));
            sum_hi += acc[2] + acc[3];
            sq_hi  += acc[2] * acc[2] + acc[3] * acc[3];
            mx_hi   = fmaxf(mx_hi, fmaxf(acc[2], acc[3]));
        }
        __syncthreads();
    }
    #pragma unroll
    for (int off = 1; off <= 2; off <<= 1) {
        sum_lo += __shfl_xor_sync(0xffffffffu, sum_lo, off);
        sq_lo  += __shfl_xor_sync(0xffffffffu, sq_lo,  off);
        mx_lo   = fmaxf(mx_lo, __shfl_xor_sync(0xffffffffu, mx_lo, off));
        sum_hi += __shfl_xor_sync(0xffffffffu, sum_hi, off);
        sq_hi  += __shfl_xor_sync(0xffffffffu, sq_hi,  off);
        mx_hi   = fmaxf(mx_hi, __shfl_xor_sync(0xffffffffu, mx_hi, off));
    }
    float mean = sum_lo / (float)Ss;
    float var  = fmaxf((sq_lo - sum_lo * mean) / (float)(Ss - 1), 0.f);
    float c_lo = SCALE / sqrtf(var + EPSF), m_lo = mx_lo;
    mean = sum_hi / (float)Ss;
    var  = fmaxf((sq_hi - sum_hi * mean) / (float)(Ss - 1), 0.f);
    float c_hi = SCALE / sqrtf(var + EPSF), m_hi = mx_hi;

    // ---- phase B: recompute + softmax + PV ----
    float oacc[8][4];
    #pragma unroll
    for (int i = 0; i < 8; i++)
        oacc[i][0] = oacc[i][1] = oacc[i][2] = oacc[i][3] = 0.f;
    float den_lo = 0.f, den_hi = 0.f;

    for (int st = 0; st < 16; st++) {
        const uint4* ksrc = kbase + st * 1024;
        #pragma unroll
        for (int i = 0; i < 4; i++) {
            int idx = t + i * 256;
            *(uint4*)&Ksm[(idx >> 3) * 72 + (idx & 7) * 8] = ksrc[idx];
        }
        #pragma unroll
        for (int i = 0; i < 4; i++) {
            int idx = t + i * 256;
            int e = idx >> 4, seg = idx & 15;
            *(uint4*)&Vsm[e * 136 + seg * 8] = vbase[e * 256 + st * 16 + seg];
        }
        __syncthreads();

        uint32_t ap[8][4];
        #pragma unroll
        for (int j = 0; j < 16; j++) {
            float acc[4] = {0.f, 0.f, 0.f, 0.f};
            uint32_t addr = ksb + (uint32_t)((j * 8 + (lane & 7)) * 72 + (lane >> 3) * 8) * 2;
            uint32_t b0, b1, b2, b3, b4, b5, b6, b7;
            LDMX4(b0, b1, b2, b3, addr);
            LDMX4(b4, b5, b6, b7, addr + 64);
            mma16816(acc, aq[0], b0, b1);
            mma16816(acc, aq[1], b2, b3);
            mma16816(acc, aq[2], b4, b5);
            mma16816(acc, aq[3], b6, b7);
            float e0 = __expf(c_lo * (acc[0] - m_lo));
            float e1 = __expf(c_lo * (acc[1] - m_lo));
            float e2 = __expf(c_hi * (acc[2] - m_hi));
            float e3 = __expf(c_hi * (acc[3] - m_hi));
            den_lo += e0 + e1;
            den_hi += e2 + e3;
            __half2 p01 = __floats2half2_rn(e0, e1);
            __half2 p23 = __floats2half2_rn(e2, e3);
            ap[j >> 1][(j & 1) * 2 + 0] = *(uint32_t*)&p01;
            ap[j >> 1][(j & 1) * 2 + 1] = *(uint32_t*)&p23;
        }
        #pragma unroll
        for (int kpp = 0; kpp < 4; kpp++) {
            #pragma unroll
            for (int dn = 0; dn < 8; dn++) {
                uint32_t addr = vsb +
                    (uint32_t)((dn * 8 + (lane & 7)) * 136 + kpp * 32 + (lane >> 3) * 8) * 2;
                uint32_t b0, b1, b2, b3;
                LDMX4(b0, b1, b2, b3, addr);
                mma16816(oacc[dn], ap[2 * kpp],     b0, b1);
                mma16816(oacc[dn], ap[2 * kpp + 1], b2, b3);
            }
        }
        __syncthreads();
    }
    #pragma unroll
    for (int off = 1; off <= 2; off <<= 1) {
        den_lo += __shfl_xor_sync(0xffffffffu, den_lo, off);
        den_hi += __shfl_xor_sync(0xffffffffu, den_hi, off);
    }
    float inv_lo = 1.f / den_lo, inv_hi = 1.f / den_hi;
    int row_lo = l0 + wrow + g, row_hi = row_lo + 8;
    float* plo = out + (((size_t)b * Ll + row_lo) * Hh + h) * Ee;
    float* phi = out + (((size_t)b * Ll + row_hi) * Hh + h) * Ee;
    #pragma unroll
    for (int dn = 0; dn < 8; dn++) {
        int d = dn * 8 + tig * 2;
        *(float2*)&plo[d] = make_float2(oacc[dn][0] * inv_lo, oacc[dn][1] * inv_lo);
        *(float2*)&phi[d] = make_float2(oacc[dn][2] * inv_hi, oacc[dn][3] * inv_hi);
    }
}

// ---------------- launch ----------------------------------------------------
extern "C" void kernel_launch(void* const* d_in, const int* in_sizes, int n_in,
                              void* d_out, int out_size)
{
    const float* q  = (const float*)d_in[0];
    const float* k  = (const float*)d_in[1];
    const float* v  = (const float*)d_in[2];
    // d_in[3] attn_mask: unused (mask_flag=False)
    const float* dw = (const float*)d_in[4];
    const float* dp = (const float*)d_in[5];
    float* out = (float*)d_out;

    transform_kernel<<<4096, 256>>>(q, k, dw, dp);
    vtrans_kernel<<<dim3(Ss / 64, BH), 256>>>(v);
    attn_kernel<<<dim3(Ll / 128, BH), 256>>>(out);
}

// round 13
// speedup vs baseline: 5.0261x; 1.0585x over previous
#include <cuda_runtime.h>
#include <cuda_fp16.h>
#include <math.h>
#include <stdint.h>

#define Bsz 4
#define Hh  8
#define Ll  2048
#define Ss  2048
#define Ee  64
#define BH  32
#define EPSF 1e-6f
#define SCALE 0.125f   /* 1/sqrt(64) */

// ---------------- scratch (static __device__, no allocation) ----------------
__device__ __half g_qt[(size_t)BH * Ll * Ee];   // [bh][l][e]
__device__ __half g_kt[(size_t)BH * Ss * Ee];   // [bh][s][e]
__device__ __half g_vt[(size_t)BH * Ee * Ss];   // [bh][e][s]  (V transposed)
__device__ float  g_G[BH * 64 * 64];            // Gram K^T K per bh
__device__ float  g_ksum[BH * 64];              // column sums of K per bh
__device__ float  g_kmax2[BH];                  // max_s ||k_s||^2 per bh
__device__ float  g_c[BH * Ll];                 // scale / tau per row
__device__ float  g_m[BH * Ll];                 // row max bound

// ---------------- PTX helpers (base-target instructions only) ---------------
__device__ __forceinline__ uint32_t smem_u32(const void* p) {
    uint32_t a;
    asm("{ .reg .u64 t; cvta.to.shared.u64 t, %1; cvt.u32.u64 %0, t; }" : "=r"(a) : "l"(p));
    return a;
}

#define LDMX4(r0, r1, r2, r3, addr) \
    asm volatile("ldmatrix.sync.aligned.m8n8.x4.shared.b16 {%0,%1,%2,%3}, [%4];" \
        : "=r"(r0), "=r"(r1), "=r"(r2), "=r"(r3) : "r"(addr))

__device__ __forceinline__ void mma16816(float* d, const uint32_t* a,
                                         uint32_t b0, uint32_t b1) {
    asm volatile("mma.sync.aligned.m16n8k16.row.col.f32.f16.f16.f32 "
        "{%0,%1,%2,%3},{%4,%5,%6,%7},{%8,%9},{%0,%1,%2,%3};"
        : "+f"(d[0]), "+f"(d[1]), "+f"(d[2]), "+f"(d[3])
        : "r"(a[0]), "r"(a[1]), "r"(a[2]), "r"(a[3]), "r"(b0), "r"(b1));
}

// ---------------- K0: zero stat accumulators (graph-replay safe) ------------
__global__ __launch_bounds__(256) void init_kernel() {
    int i = blockIdx.x * 256 + threadIdx.x;
    if (i < BH * 64 * 64) g_G[i] = 0.f;
    if (i < BH * 64)      g_ksum[i] = 0.f;
    if (i < BH)           g_kmax2[i] = 0.f;
}

// ---------------- K1: std over H (axis=-2 of [B,L,H,E]) + tanh, fp16 out ---
__global__ __launch_bounds__(256) void transform_kernel(
    const float* __restrict__ qg, const float* __restrict__ kg,
    const float* __restrict__ dw, const float* __restrict__ dp)
{
    const int NPT = Bsz * Ll * Ee;
    int gid = blockIdx.x * blockDim.x + threadIdx.x;
    int which = (gid >= NPT) ? 1 : 0;
    int id = gid - which * NPT;
    const float* x  = which ? kg   : qg;
    __half*      xt = which ? g_kt : g_qt;

    int e  = id & 63;
    int bl = id >> 6;
    int b  = bl >> 11, l = bl & 2047;

    const float* base = x + ((size_t)bl * Hh) * Ee + e;
    float v[Hh];
    float s1 = 0.f;
    #pragma unroll
    for (int h = 0; h < Hh; h++) { v[h] = base[h * Ee]; s1 += v[h]; }
    float mean = s1 * (1.f / Hh);
    float s2 = 0.f;
    #pragma unroll
    for (int h = 0; h < Hh; h++) { float d = v[h] - mean; s2 += d * d; }
    float stdv = sqrtf(s2 * (1.f / (Hh - 1)));
    float sc = (1.f / (stdv + EPSF)) * dw[0];
    float p  = dp[0];

    size_t obase = (((size_t)b * Hh) * Ll + l) * Ee + e;
    #pragma unroll
    for (int h = 0; h < Hh; h++)
        xt[obase + (size_t)h * Ll * Ee] = __float2half(tanhf(v[h] * sc) * p);
}

// ---------------- K1b: V transpose to [bh][e][s], fp16 ----------------------
__global__ __launch_bounds__(256) void vtrans_kernel(const float* __restrict__ v)
{
    __shared__ float tile[64][65];
    int bh = blockIdx.y;
    int b = bh >> 3, h = bh & 7;
    int s0 = blockIdx.x << 6;
    int t = threadIdx.x;
    int e = t & 63, sr = t >> 6;
    const float* vb = v + ((size_t)b * Ss * Hh + h) * Ee;
    #pragma unroll
    for (int i = 0; i < 16; i++) {
        int s = sr + i * 4;
        tile[s][e] = vb[(size_t)(s0 + s) * (Hh * Ee) + e];
    }
    __syncthreads();
    int sp = t & 63, er = t >> 6;
    __half* ob = g_vt + (size_t)bh * Ee * Ss;
    #pragma unroll
    for (int i = 0; i < 16; i++) {
        int e2 = er + i * 4;
        ob[(size_t)e2 * Ss + s0 + sp] = __float2half(tile[sp][e2]);
    }
}

// ---------------- K2: Gram G = K^T K, ksum, max row norm --------------------
// grid (8 s-chunks of 256, BH), 256 thr.
__global__ __launch_bounds__(256) void gram_kernel()
{
    __shared__ __half ks[128 * 64];     // 16 KB
    __shared__ float red[4 * 64];
    __shared__ float redmax[8];

    int t = threadIdx.x, lane = t & 31;
    int bh = blockIdx.y, s0 = blockIdx.x << 8;
    int tx = t & 15, ty = t >> 4;
    int e = t & 63, q4 = t >> 6;

    float acc[4][4] = {};
    float psum = 0.f, pmax = 0.f;
    const uint4* kb = (const uint4*)(g_kt + ((size_t)bh * Ss + s0) * Ee);

    #pragma unroll
    for (int hlf = 0; hlf < 2; hlf++) {
        #pragma unroll
        for (int i = 0; i < 4; i++) {
            int idx = t + i * 256;
            ((uint4*)ks)[idx] = kb[hlf * 1024 + idx];
        }
        __syncthreads();
        for (int s = 0; s < 128; s++) {
            float a[4], bb[4];
            #pragma unroll
            for (int i = 0; i < 4; i++) a[i]  = __half2float(ks[s * 64 + ty * 4 + i]);
            #pragma unroll
            for (int j = 0; j < 4; j++) bb[j] = __half2float(ks[s * 64 + tx * 4 + j]);
            #pragma unroll
            for (int i = 0; i < 4; i++)
                #pragma unroll
                for (int j = 0; j < 4; j++)
                    acc[i][j] += a[i] * bb[j];
        }
        for (int s = q4; s < 128; s += 4) psum += __half2float(ks[s * 64 + e]);
        if (t < 128) {
            float n2 = 0.f;
            const __half2* rp = (const __half2*)(ks + t * 64);
            #pragma unroll
            for (int i = 0; i < 32; i++) {
                float2 f = __half22float2(rp[i]);
                n2 += f.x * f.x + f.y * f.y;
            }
            pmax = fmaxf(pmax, n2);
        }
        __syncthreads();
    }
    #pragma unroll
    for (int i = 0; i < 4; i++)
        #pragma unroll
        for (int j = 0; j < 4; j++)
            atomicAdd(&g_G[bh * 4096 + (ty * 4 + i) * 64 + tx * 4 + j], acc[i][j]);

    red[q4 * 64 + e] = psum;
    #pragma unroll
    for (int off = 16; off; off >>= 1)
        pmax = fmaxf(pmax, __shfl_xor_sync(0xffffffffu, pmax, off));
    if (lane == 0) redmax[t >> 5] = pmax;
    __syncthreads();
    if (t < 64)
        atomicAdd(&g_ksum[bh * 64 + t], red[t] + red[64 + t] + red[128 + t] + red[192 + t]);
    if (t == 0) {
        float m = 0.f;
        #pragma unroll
        for (int w = 0; w < 8; w++) m = fmaxf(m, redmax[w]);
        atomicMax((int*)&g_kmax2[bh], __float_as_int(m));   // all values >= 0
    }
}

// ---------------- K3: per-row c = scale/tau, m = ||q||*max||k|| -------------
// grid (Ll/128, BH), 256 thr. tmp = Q*G (reg-tiled fp32), then row dots.
__global__ __launch_bounds__(256) void stats_kernel()
{
    __shared__ __half Qs[128 * 72];     // 18432 B
    __shared__ float  Gs[64 * 65];      // 16640 B
    __shared__ float  ksm[64];
    __shared__ float  km2s;

    int t = threadIdx.x;
    int bh = blockIdx.y, l0 = blockIdx.x << 7;

    const uint4* qsrc = (const uint4*)(g_qt + ((size_t)bh * Ll + l0) * Ee);
    #pragma unroll
    for (int i = 0; i < 4; i++) {
        int idx = t + i * 256;
        *(uint4*)&Qs[(idx >> 3) * 72 + (idx & 7) * 8] = qsrc[idx];
    }
    #pragma unroll
    for (int i = 0; i < 16; i++) {
        int idx = t + i * 256;
        Gs[(idx >> 6) * 65 + (idx & 63)] = g_G[bh * 4096 + idx];
    }
    if (t < 64) ksm[t] = g_ksum[bh * 64 + t];
    if (t == 0) km2s = g_kmax2[bh];
    __syncthreads();

    int tx = t & 15, ty = t >> 4;
    float kmax = sqrtf(km2s);

    #pragma unroll
    for (int pass = 0; pass < 2; pass++) {
        int rbase = pass * 64 + ty * 4;
        float acc[4][4] = {};
        for (int k = 0; k < 64; k++) {
            float a[4], bb[4];
            #pragma unroll
            for (int i = 0; i < 4; i++) a[i]  = __half2float(Qs[(rbase + i) * 72 + k]);
            #pragma unroll
            for (int j = 0; j < 4; j++) bb[j] = Gs[(tx * 4 + j) * 65 + k];
            #pragma unroll
            for (int i = 0; i < 4; i++)
                #pragma unroll
                for (int j = 0; j < 4; j++)
                    acc[i][j] += a[i] * bb[j];
        }
        #pragma unroll
        for (int i = 0; i < 4; i++) {
            float qv[4];
            #pragma unroll
            for (int j = 0; j < 4; j++)
                qv[j] = __half2float(Qs[(rbase + i) * 72 + tx * 4 + j]);
            float psq  = acc[i][0]*qv[0] + acc[i][1]*qv[1] + acc[i][2]*qv[2] + acc[i][3]*qv[3];
            float psum = qv[0]*ksm[tx*4] + qv[1]*ksm[tx*4+1] + qv[2]*ksm[tx*4+2] + qv[3]*ksm[tx*4+3];
            float pnrm = qv[0]*qv[0] + qv[1]*qv[1] + qv[2]*qv[2] + qv[3]*qv[3];
            #pragma unroll
            for (int off = 1; off <= 8; off <<= 1) {
                psq  += __shfl_xor_sync(0xffffffffu, psq,  off);
                psum += __shfl_xor_sync(0xffffffffu, psum, off);
                pnrm += __shfl_xor_sync(0xffffffffu, pnrm, off);
            }
            if (tx == 0) {
                float mean = psum / (float)Ss;
                float var  = fmaxf((psq - psum * mean) / (float)(Ss - 1), 0.f);
                int row = bh * Ll + l0 + rbase + i;
                g_c[row] = SCALE / sqrtf(var + EPSF);
                g_m[row] = sqrtf(pnrm) * kmax;     // upper bound on row max
            }
        }
    }
}

// ---------------- K4: single-pass flash attention (mma.sync HMMA) -----------
// grid (Ll/128, BH), 256 thr = 8 warps, 16 L-rows/warp.
__global__ __launch_bounds__(256) void attn_kernel(float* __restrict__ out)
{
    __shared__ __align__(16) __half Ksm[128 * 72];   // 18432 B
    __shared__ __align__(16) __half Vsm[64 * 136];   // 17408 B
    __shared__ float csm[128], msm[128];

    int t = threadIdx.x, lane = t & 31, wid = t >> 5;
    int bh = blockIdx.y, l0 = blockIdx.x << 7;
    int b = bh >> 3, h = bh & 7;
    int wrow = wid * 16;
    int g = lane >> 2, tig = lane & 3;

    uint32_t ksb = smem_u32(Ksm), vsb = smem_u32(Vsm);

    if (t < 128) {
        csm[t] = g_c[bh * Ll + l0 + t];
        msm[t] = g_m[bh * Ll + l0 + t];
    }

    // ---- stage Q tile into Ksm, load resident A fragments ----
    {
        const uint4* qsrc = (const uint4*)(g_qt + ((size_t)bh * Ll + l0) * Ee);
        #pragma unroll
        for (int i = 0; i < 4; i++) {
            int idx = t + i * 256;
            *(uint4*)&Ksm[(idx >> 3) * 72 + (idx & 7) * 8] = qsrc[idx];
        }
    }
    __syncthreads();
    uint32_t aq[4][4];
    {
        int r  = wrow + ((lane >> 3) & 1) * 8 + (lane & 7);
        int cb = ((lane >> 4) & 1) * 8;
        #pragma unroll
        for (int kk = 0; kk < 4; kk++) {
            uint32_t addr = ksb + (uint32_t)(r * 72 + kk * 16 + cb) * 2;
            LDMX4(aq[kk][0], aq[kk][1], aq[kk][2], aq[kk][3], addr);
        }
    }
    __syncthreads();

    float c_lo = csm[wrow + g],     m_lo = msm[wrow + g];
    float c_hi = csm[wrow + g + 8], m_hi = msm[wrow + g + 8];

    const uint4* kbase = (const uint4*)(g_kt + (size_t)bh * Ss * Ee);
    const uint4* vbase = (const uint4*)(g_vt + (size_t)bh * Ee * Ss);

    float oacc[8][4];
    #pragma unroll
    for (int i = 0; i < 8; i++)
        oacc[i][0] = oacc[i][1] = oacc[i][2] = oacc[i][3] = 0.f;
    float den_lo = 0.f, den_hi = 0.f;

    for (int st = 0; st < 16; st++) {
        const uint4* ksrc = kbase + st * 1024;
        #pragma unroll
        for (int i = 0; i < 4; i++) {
            int idx = t + i * 256;
            *(uint4*)&Ksm[(idx >> 3) * 72 + (idx & 7) * 8] = ksrc[idx];
        }
        #pragma unroll
        for (int i = 0; i < 4; i++) {
            int idx = t + i * 256;
            int e = idx >> 4, seg = idx & 15;
            *(uint4*)&Vsm[e * 136 + seg * 8] = vbase[e * 256 + st * 16 + seg];
        }
        __syncthreads();

        uint32_t ap[8][4];
        #pragma unroll
        for (int j = 0; j < 16; j++) {
            float acc[4] = {0.f, 0.f, 0.f, 0.f};
            uint32_t addr = ksb + (uint32_t)((j * 8 + (lane & 7)) * 72 + (lane >> 3) * 8) * 2;
            uint32_t b0, b1, b2, b3, b4, b5, b6, b7;
            LDMX4(b0, b1, b2, b3, addr);
            LDMX4(b4, b5, b6, b7, addr + 64);
            mma16816(acc, aq[0], b0, b1);
            mma16816(acc, aq[1], b2, b3);
            mma16816(acc, aq[2], b4, b5);
            mma16816(acc, aq[3], b6, b7);
            float e0 = __expf(c_lo * (acc[0] - m_lo));
            float e1 = __expf(c_lo * (acc[1] - m_lo));
            float e2 = __expf(c_hi * (acc[2] - m_hi));
            float e3 = __expf(c_hi * (acc[3] - m_hi));
            den_lo += e0 + e1;
            den_hi += e2 + e3;
            __half2 p01 = __floats2half2_rn(e0, e1);
            __half2 p23 = __floats2half2_rn(e2, e3);
            ap[j >> 1][(j & 1) * 2 + 0] = *(uint32_t*)&p01;
            ap[j >> 1][(j & 1) * 2 + 1] = *(uint32_t*)&p23;
        }
        #pragma unroll
        for (int kpp = 0; kpp < 4; kpp++) {
            #pragma unroll
            for (int dn = 0; dn < 8; dn++) {
                uint32_t addr = vsb +
                    (uint32_t)((dn * 8 + (lane & 7)) * 136 + kpp * 32 + (lane >> 3) * 8) * 2;
                uint32_t b0, b1, b2, b3;
                LDMX4(b0, b1, b2, b3, addr);
                mma16816(oacc[dn], ap[2 * kpp],     b0, b1);
                mma16816(oacc[dn], ap[2 * kpp + 1], b2, b3);
            }
        }
        __syncthreads();
    }
    #pragma unroll
    for (int off = 1; off <= 2; off <<= 1) {
        den_lo += __shfl_xor_sync(0xffffffffu, den_lo, off);
        den_hi += __shfl_xor_sync(0xffffffffu, den_hi, off);
    }
    float inv_lo = 1.f / den_lo, inv_hi = 1.f / den_hi;
    int row_lo = l0 + wrow + g, row_hi = row_lo + 8;
    float* plo = out + (((size_t)b * Ll + row_lo) * Hh + h) * Ee;
    float* phi = out + (((size_t)b * Ll + row_hi) * Hh + h) * Ee;
    #pragma unroll
    for (int dn = 0; dn < 8; dn++) {
        int d = dn * 8 + tig * 2;
        *(float2*)&plo[d] = make_float2(oacc[dn][0] * inv_lo, oacc[dn][1] * inv_lo);
        *(float2*)&phi[d] = make_float2(oacc[dn][2] * inv_hi, oacc[dn][3] * inv_hi);
    }
}

// ---------------- launch ----------------------------------------------------
extern "C" void kernel_launch(void* const* d_in, const int* in_sizes, int n_in,
                              void* d_out, int out_size)
{
    const float* q  = (const float*)d_in[0];
    const float* k  = (const float*)d_in[1];
    const float* v  = (const float*)d_in[2];
    // d_in[3] attn_mask: unused (mask_flag=False)
    const float* dw = (const float*)d_in[4];
    const float* dp = (const float*)d_in[5];
    float* out = (float*)d_out;

    init_kernel<<<(BH * 64 * 64 + 255) / 256, 256>>>();
    transform_kernel<<<4096, 256>>>(q, k, dw, dp);
    vtrans_kernel<<<dim3(Ss / 64, BH), 256>>>(v);
    gram_kernel<<<dim3(8, BH), 256>>>();
    stats_kernel<<<dim3(Ll / 128, BH), 256>>>();
    attn_kernel<<<dim3(Ll / 128, BH), 256>>>(out);
}

// round 14
// speedup vs baseline: 6.0363x; 1.2010x over previous
#include <cuda_runtime.h>
#include <cuda_fp16.h>
#include <math.h>
#include <stdint.h>

#define Bsz 4
#define Hh  8
#define Ll  2048
#define Ss  2048
#define Ee  64
#define BH  32
#define EPSF 1e-6f
#define SCALE 0.125f   /* 1/sqrt(64) */

// ---------------- scratch (static __device__, no allocation) ----------------
__device__ __half g_qt[(size_t)BH * Ll * Ee];   // [bh][l][e]
__device__ __half g_kt[(size_t)BH * Ss * Ee];   // [bh][s][e]
__device__ __half g_vt[(size_t)BH * Ee * Ss];   // [bh][e][s]  (V transposed)
__device__ float  g_G[BH * 64 * 64];            // Gram K^T K per bh
__device__ float  g_ksum[BH * 64];              // column sums of K per bh
__device__ float  g_kmax2[BH];                  // max_s ||k_s||^2 per bh
__device__ float  g_c[BH * Ll];                 // scale / tau per row
__device__ float  g_m[BH * Ll];                 // row max bound

// ---------------- PTX helpers (base-target instructions only) ---------------
__device__ __forceinline__ uint32_t smem_u32(const void* p) {
    uint32_t a;
    asm("{ .reg .u64 t; cvta.to.shared.u64 t, %1; cvt.u32.u64 %0, t; }" : "=r"(a) : "l"(p));
    return a;
}

#define LDMX4(r0, r1, r2, r3, addr) \
    asm volatile("ldmatrix.sync.aligned.m8n8.x4.shared.b16 {%0,%1,%2,%3}, [%4];" \
        : "=r"(r0), "=r"(r1), "=r"(r2), "=r"(r3) : "r"(addr))

__device__ __forceinline__ void mma16816(float* d, const uint32_t* a,
                                         uint32_t b0, uint32_t b1) {
    asm volatile("mma.sync.aligned.m16n8k16.row.col.f32.f16.f16.f32 "
        "{%0,%1,%2,%3},{%4,%5,%6,%7},{%8,%9},{%0,%1,%2,%3};"
        : "+f"(d[0]), "+f"(d[1]), "+f"(d[2]), "+f"(d[3])
        : "r"(a[0]), "r"(a[1]), "r"(a[2]), "r"(a[3]), "r"(b0), "r"(b1));
}

#define CPA16(dst, src) \
    asm volatile("cp.async.cg.shared.global [%0], [%1], 16;" :: "r"(dst), "l"(src))
#define CPA_COMMIT() asm volatile("cp.async.commit_group;" ::: "memory")
#define CPA_WAIT(n)  asm volatile("cp.async.wait_group %0;" :: "n"(n) : "memory")

// ---------------- K0: zero stat accumulators (graph-replay safe) ------------
__global__ __launch_bounds__(256) void init_kernel() {
    int i = blockIdx.x * 256 + threadIdx.x;
    if (i < BH * 64 * 64) g_G[i] = 0.f;
    if (i < BH * 64)      g_ksum[i] = 0.f;
    if (i < BH)           g_kmax2[i] = 0.f;
}

// ---------------- K1: std over H (axis=-2 of [B,L,H,E]) + tanh, fp16 out ---
__global__ __launch_bounds__(256) void transform_kernel(
    const float* __restrict__ qg, const float* __restrict__ kg,
    const float* __restrict__ dw, const float* __restrict__ dp)
{
    const int NPT = Bsz * Ll * Ee;
    int gid = blockIdx.x * blockDim.x + threadIdx.x;
    int which = (gid >= NPT) ? 1 : 0;
    int id = gid - which * NPT;
    const float* x  = which ? kg   : qg;
    __half*      xt = which ? g_kt : g_qt;

    int e  = id & 63;
    int bl = id >> 6;
    int b  = bl >> 11, l = bl & 2047;

    const float* base = x + ((size_t)bl * Hh) * Ee + e;
    float v[Hh];
    float s1 = 0.f;
    #pragma unroll
    for (int h = 0; h < Hh; h++) { v[h] = base[h * Ee]; s1 += v[h]; }
    float mean = s1 * (1.f / Hh);
    float s2 = 0.f;
    #pragma unroll
    for (int h = 0; h < Hh; h++) { float d = v[h] - mean; s2 += d * d; }
    float stdv = sqrtf(s2 * (1.f / (Hh - 1)));
    float sc = (1.f / (stdv + EPSF)) * dw[0];
    float p  = dp[0];

    size_t obase = (((size_t)b * Hh) * Ll + l) * Ee + e;
    #pragma unroll
    for (int h = 0; h < Hh; h++)
        xt[obase + (size_t)h * Ll * Ee] = __float2half(tanhf(v[h] * sc) * p);
}

// ---------------- K1b: V transpose to [bh][e][s], fp16 ----------------------
__global__ __launch_bounds__(256) void vtrans_kernel(const float* __restrict__ v)
{
    __shared__ float tile[64][65];
    int bh = blockIdx.y;
    int b = bh >> 3, h = bh & 7;
    int s0 = blockIdx.x << 6;
    int t = threadIdx.x;
    int e = t & 63, sr = t >> 6;
    const float* vb = v + ((size_t)b * Ss * Hh + h) * Ee;
    #pragma unroll
    for (int i = 0; i < 16; i++) {
        int s = sr + i * 4;
        tile[s][e] = vb[(size_t)(s0 + s) * (Hh * Ee) + e];
    }
    __syncthreads();
    int sp = t & 63, er = t >> 6;
    __half* ob = g_vt + (size_t)bh * Ee * Ss;
    #pragma unroll
    for (int i = 0; i < 16; i++) {
        int e2 = er + i * 4;
        ob[(size_t)e2 * Ss + s0 + sp] = __float2half(tile[sp][e2]);
    }
}

// ---------------- K2: Gram G = K^T K, ksum, max row norm --------------------
// grid (32 s-chunks of 64, BH), 256 thr. 4x more CTAs than before: latency hiding.
__global__ __launch_bounds__(256) void gram_kernel()
{
    __shared__ __half ks[64 * 64];      // 8 KB
    __shared__ float red[4 * 64];
    __shared__ float redmax[8];

    int t = threadIdx.x, lane = t & 31;
    int bh = blockIdx.y, s0 = blockIdx.x << 6;
    int tx = t & 15, ty = t >> 4;
    int e = t & 63, q4 = t >> 6;

    const uint4* kb = (const uint4*)(g_kt + ((size_t)bh * Ss + s0) * Ee);
    ((uint4*)ks)[t]       = kb[t];
    ((uint4*)ks)[t + 256] = kb[t + 256];
    __syncthreads();

    float acc[4][4] = {};
    for (int s = 0; s < 64; s++) {
        float a[4], bb[4];
        #pragma unroll
        for (int i = 0; i < 4; i++) a[i]  = __half2float(ks[s * 64 + ty * 4 + i]);
        #pragma unroll
        for (int j = 0; j < 4; j++) bb[j] = __half2float(ks[s * 64 + tx * 4 + j]);
        #pragma unroll
        for (int i = 0; i < 4; i++)
            #pragma unroll
            for (int j = 0; j < 4; j++)
                acc[i][j] += a[i] * bb[j];
    }
    float psum = 0.f, pmax = 0.f;
    #pragma unroll
    for (int s4 = 0; s4 < 16; s4++) psum += __half2float(ks[(q4 + s4 * 4) * 64 + e]);
    if (t < 64) {
        float n2 = 0.f;
        const __half2* rp = (const __half2*)(ks + t * 64);
        #pragma unroll
        for (int i = 0; i < 32; i++) {
            float2 f = __half22float2(rp[i]);
            n2 += f.x * f.x + f.y * f.y;
        }
        pmax = n2;
    }

    #pragma unroll
    for (int i = 0; i < 4; i++)
        #pragma unroll
        for (int j = 0; j < 4; j++)
            atomicAdd(&g_G[bh * 4096 + (ty * 4 + i) * 64 + tx * 4 + j], acc[i][j]);

    red[q4 * 64 + e] = psum;
    #pragma unroll
    for (int off = 16; off; off >>= 1)
        pmax = fmaxf(pmax, __shfl_xor_sync(0xffffffffu, pmax, off));
    if (lane == 0) redmax[t >> 5] = pmax;
    __syncthreads();
    if (t < 64)
        atomicAdd(&g_ksum[bh * 64 + t], red[t] + red[64 + t] + red[128 + t] + red[192 + t]);
    if (t == 0) {
        float m = 0.f;
        #pragma unroll
        for (int w = 0; w < 8; w++) m = fmaxf(m, redmax[w]);
        atomicMax((int*)&g_kmax2[bh], __float_as_int(m));   // all values >= 0
    }
}

// ---------------- K3: per-row c = scale/tau, m = ||q||*max||k|| -------------
__global__ __launch_bounds__(256) void stats_kernel()
{
    __shared__ __half Qs[128 * 72];     // 18432 B
    __shared__ float  Gs[64 * 65];      // 16640 B
    __shared__ float  ksm[64];
    __shared__ float  km2s;

    int t = threadIdx.x;
    int bh = blockIdx.y, l0 = blockIdx.x << 7;

    const uint4* qsrc = (const uint4*)(g_qt + ((size_t)bh * Ll + l0) * Ee);
    #pragma unroll
    for (int i = 0; i < 4; i++) {
        int idx = t + i * 256;
        *(uint4*)&Qs[(idx >> 3) * 72 + (idx & 7) * 8] = qsrc[idx];
    }
    #pragma unroll
    for (int i = 0; i < 16; i++) {
        int idx = t + i * 256;
        Gs[(idx >> 6) * 65 + (idx & 63)] = g_G[bh * 4096 + idx];
    }
    if (t < 64) ksm[t] = g_ksum[bh * 64 + t];
    if (t == 0) km2s = g_kmax2[bh];
    __syncthreads();

    int tx = t & 15, ty = t >> 4;
    float kmax = sqrtf(km2s);

    #pragma unroll
    for (int pass = 0; pass < 2; pass++) {
        int rbase = pass * 64 + ty * 4;
        float acc[4][4] = {};
        for (int k = 0; k < 64; k++) {
            float a[4], bb[4];
            #pragma unroll
            for (int i = 0; i < 4; i++) a[i]  = __half2float(Qs[(rbase + i) * 72 + k]);
            #pragma unroll
            for (int j = 0; j < 4; j++) bb[j] = Gs[(tx * 4 + j) * 65 + k];
            #pragma unroll
            for (int i = 0; i < 4; i++)
                #pragma unroll
                for (int j = 0; j < 4; j++)
                    acc[i][j] += a[i] * bb[j];
        }
        #pragma unroll
        for (int i = 0; i < 4; i++) {
            float qv[4];
            #pragma unroll
            for (int j = 0; j < 4; j++)
                qv[j] = __half2float(Qs[(rbase + i) * 72 + tx * 4 + j]);
            float psq  = acc[i][0]*qv[0] + acc[i][1]*qv[1] + acc[i][2]*qv[2] + acc[i][3]*qv[3];
            float psum = qv[0]*ksm[tx*4] + qv[1]*ksm[tx*4+1] + qv[2]*ksm[tx*4+2] + qv[3]*ksm[tx*4+3];
            float pnrm = qv[0]*qv[0] + qv[1]*qv[1] + qv[2]*qv[2] + qv[3]*qv[3];
            #pragma unroll
            for (int off = 1; off <= 8; off <<= 1) {
                psq  += __shfl_xor_sync(0xffffffffu, psq,  off);
                psum += __shfl_xor_sync(0xffffffffu, psum, off);
                pnrm += __shfl_xor_sync(0xffffffffu, pnrm, off);
            }
            if (tx == 0) {
                float mean = psum / (float)Ss;
                float var  = fmaxf((psq - psum * mean) / (float)(Ss - 1), 0.f);
                int row = bh * Ll + l0 + rbase + i;
                g_c[row] = SCALE / sqrtf(var + EPSF);
                g_m[row] = sqrtf(pnrm) * kmax;     // upper bound on row max
            }
        }
    }
}

// ---------------- K4: single-pass flash attention, cp.async pipelined -------
// grid (Ll/128, BH), 256 thr = 8 warps, 16 L-rows/warp. Dynamic smem 72 KB:
// K[2][128*72]h | V[2][64*136]h | c[128]f | m[128]f.
#define KBUF 18432
#define VBUF 17408

__device__ __forceinline__ void load_k_tile(uint32_t kdst, const uint4* ksrc, int t) {
    #pragma unroll
    for (int i = 0; i < 4; i++) {
        int idx = t + i * 256;
        uint32_t dst = kdst + (uint32_t)((idx >> 3) * 72 + (idx & 7) * 8) * 2;
        CPA16(dst, ksrc + idx);
    }
}
__device__ __forceinline__ void load_v_tile(uint32_t vdst, const uint4* vsrc, int st, int t) {
    #pragma unroll
    for (int i = 0; i < 4; i++) {
        int idx = t + i * 256;
        int e = idx >> 4, seg = idx & 15;
        uint32_t dst = vdst + (uint32_t)(e * 136 + seg * 8) * 2;
        CPA16(dst, vsrc + e * 256 + st * 16 + seg);
    }
}

__global__ __launch_bounds__(256) void attn_kernel(float* __restrict__ out)
{
    extern __shared__ __align__(16) char dyn[];
    __half* Ksm = (__half*)dyn;
    __half* Vsm = (__half*)(dyn + 2 * KBUF);
    float*  csm = (float*)(dyn + 2 * KBUF + 2 * VBUF);
    float*  msm = csm + 128;

    int t = threadIdx.x, lane = t & 31, wid = t >> 5;
    int bh = blockIdx.y, l0 = blockIdx.x << 7;
    int b = bh >> 3, h = bh & 7;
    int wrow = wid * 16;
    int g = lane >> 2, tig = lane & 3;

    uint32_t ksb = smem_u32(Ksm), vsb = smem_u32(Vsm);

    const uint4* kbase = (const uint4*)(g_kt + (size_t)bh * Ss * Ee);
    const uint4* vbase = (const uint4*)(g_vt + (size_t)bh * Ee * Ss);

    // prefetch tile 0 into buffer 0 while we stage Q into buffer 1
    load_k_tile(ksb, kbase, t);
    load_v_tile(vsb, vbase, 0, t);
    CPA_COMMIT();

    if (t < 128) {
        csm[t] = g_c[bh * Ll + l0 + t];
        msm[t] = g_m[bh * Ll + l0 + t];
    }
    {
        const uint4* qsrc = (const uint4*)(g_qt + ((size_t)bh * Ll + l0) * Ee);
        #pragma unroll
        for (int i = 0; i < 4; i++) {
            int idx = t + i * 256;
            *(uint4*)&Ksm[KBUF / 2 + (idx >> 3) * 72 + (idx & 7) * 8] = qsrc[idx];
        }
    }
    __syncthreads();
    uint32_t aq[4][4];
    {
        int r  = wrow + ((lane >> 3) & 1) * 8 + (lane & 7);
        int cb = ((lane >> 4) & 1) * 8;
        #pragma unroll
        for (int kk = 0; kk < 4; kk++) {
            uint32_t addr = ksb + KBUF + (uint32_t)(r * 72 + kk * 16 + cb) * 2;
            LDMX4(aq[kk][0], aq[kk][1], aq[kk][2], aq[kk][3], addr);
        }
    }
    __syncthreads();   // everyone done reading Q from buffer 1 before tile-1 prefetch

    float c_lo = csm[wrow + g],     m_lo = msm[wrow + g];
    float c_hi = csm[wrow + g + 8], m_hi = msm[wrow + g + 8];

    float oacc[8][4];
    #pragma unroll
    for (int i = 0; i < 8; i++)
        oacc[i][0] = oacc[i][1] = oacc[i][2] = oacc[i][3] = 0.f;
    float den_lo = 0.f, den_hi = 0.f;

    for (int st = 0; st < 16; st++) {
        if (st < 15) {
            uint32_t nb = (uint32_t)((st + 1) & 1);
            load_k_tile(ksb + nb * KBUF, kbase + (st + 1) * 1024, t);
            load_v_tile(vsb + nb * VBUF, vbase, st + 1, t);
            CPA_COMMIT();
            CPA_WAIT(1);
        } else {
            CPA_WAIT(0);
        }
        __syncthreads();

        uint32_t kb2 = ksb + (uint32_t)(st & 1) * KBUF;
        uint32_t vb2 = vsb + (uint32_t)(st & 1) * VBUF;

        uint32_t ap[8][4];
        #pragma unroll
        for (int j = 0; j < 16; j++) {
            float acc[4] = {0.f, 0.f, 0.f, 0.f};
            uint32_t addr = kb2 + (uint32_t)((j * 8 + (lane & 7)) * 72 + (lane >> 3) * 8) * 2;
            uint32_t b0, b1, b2, b3, b4, b5, b6, b7;
            LDMX4(b0, b1, b2, b3, addr);
            LDMX4(b4, b5, b6, b7, addr + 64);
            mma16816(acc, aq[0], b0, b1);
            mma16816(acc, aq[1], b2, b3);
            mma16816(acc, aq[2], b4, b5);
            mma16816(acc, aq[3], b6, b7);
            float e0 = __expf(c_lo * (acc[0] - m_lo));
            float e1 = __expf(c_lo * (acc[1] - m_lo));
            float e2 = __expf(c_hi * (acc[2] - m_hi));
            float e3 = __expf(c_hi * (acc[3] - m_hi));
            den_lo += e0 + e1;
            den_hi += e2 + e3;
            __half2 p01 = __floats2half2_rn(e0, e1);
            __half2 p23 = __floats2half2_rn(e2, e3);
            ap[j >> 1][(j & 1) * 2 + 0] = *(uint32_t*)&p01;
            ap[j >> 1][(j & 1) * 2 + 1] = *(uint32_t*)&p23;
        }
        #pragma unroll
        for (int kpp = 0; kpp < 4; kpp++) {
            #pragma unroll
            for (int dn = 0; dn < 8; dn++) {
                uint32_t addr = vb2 +
                    (uint32_t)((dn * 8 + (lane & 7)) * 136 + kpp * 32 + (lane >> 3) * 8) * 2;
                uint32_t b0, b1, b2, b3;
                LDMX4(b0, b1, b2, b3, addr);
                mma16816(oacc[dn], ap[2 * kpp],     b0, b1);
                mma16816(oacc[dn], ap[2 * kpp + 1], b2, b3);
            }
        }
        __syncthreads();
    }
    #pragma unroll
    for (int off = 1; off <= 2; off <<= 1) {
        den_lo += __shfl_xor_sync(0xffffffffu, den_lo, off);
        den_hi += __shfl_xor_sync(0xffffffffu, den_hi, off);
    }
    float inv_lo = 1.f / den_lo, inv_hi = 1.f / den_hi;
    int row_lo = l0 + wrow + g, row_hi = row_lo + 8;
    float* plo = out + (((size_t)b * Ll + row_lo) * Hh + h) * Ee;
    float* phi = out + (((size_t)b * Ll + row_hi) * Hh + h) * Ee;
    #pragma unroll
    for (int dn = 0; dn < 8; dn++) {
        int d = dn * 8 + tig * 2;
        *(float2*)&plo[d] = make_float2(oacc[dn][0] * inv_lo, oacc[dn][1] * inv_lo);
        *(float2*)&phi[d] = make_float2(oacc[dn][2] * inv_hi, oacc[dn][3] * inv_hi);
    }
}

// ---------------- launch ----------------------------------------------------
extern "C" void kernel_launch(void* const* d_in, const int* in_sizes, int n_in,
                              void* d_out, int out_size)
{
    const float* q  = (const float*)d_in[0];
    const float* k  = (const float*)d_in[1];
    const float* v  = (const float*)d_in[2];
    // d_in[3] attn_mask: unused (mask_flag=False)
    const float* dw = (const float*)d_in[4];
    const float* dp = (const float*)d_in[5];
    float* out = (float*)d_out;

    const int ATTN_SMEM = 2 * KBUF + 2 * VBUF + 2 * 128 * 4;   // 72704 B
    cudaFuncSetAttribute(attn_kernel, cudaFuncAttributeMaxDynamicSharedMemorySize, ATTN_SMEM);

    init_kernel<<<(BH * 64 * 64 + 255) / 256, 256>>>();
    transform_kernel<<<4096, 256>>>(q, k, dw, dp);
    vtrans_kernel<<<dim3(Ss / 64, BH), 256>>>(v);
    gram_kernel<<<dim3(32, BH), 256>>>();
    stats_kernel<<<dim3(Ll / 128, BH), 256>>>();
    attn_kernel<<<dim3(Ll / 128, BH), 256, ATTN_SMEM>>>(out);
}

// round 16
// speedup vs baseline: 6.3009x; 1.0438x over previous
#include <cuda_runtime.h>
#include <cuda_fp16.h>
#include <math.h>
#include <stdint.h>

#define Bsz 4
#define Hh  8
#define Ll  2048
#define Ss  2048
#define Ee  64
#define BH  32
#define EPSF 1e-6f
#define SCALE 0.125f   /* 1/sqrt(64) */

// ---------------- scratch (static __device__, no allocation) ----------------
__device__ __half g_qt[(size_t)BH * Ll * Ee];   // [bh][l][e]
__device__ __half g_kt[(size_t)BH * Ss * Ee];   // [bh][s][e]
__device__ __half g_vt[(size_t)BH * Ee * Ss];   // [bh][e][s]  (V transposed)
__device__ float  g_G[BH * 64 * 64];            // Gram K^T K per bh (symmetric)
__device__ float  g_ksum[BH * 64];              // column sums of K per bh
__device__ float  g_kmax2[BH];                  // max_s ||k_s||^2 per bh

// ---------------- PTX helpers (base-target instructions only) ---------------
__device__ __forceinline__ uint32_t smem_u32(const void* p) {
    uint32_t a;
    asm("{ .reg .u64 t; cvta.to.shared.u64 t, %1; cvt.u32.u64 %0, t; }" : "=r"(a) : "l"(p));
    return a;
}

#define LDMX4(r0, r1, r2, r3, addr) \
    asm volatile("ldmatrix.sync.aligned.m8n8.x4.shared.b16 {%0,%1,%2,%3}, [%4];" \
        : "=r"(r0), "=r"(r1), "=r"(r2), "=r"(r3) : "r"(addr))

__device__ __forceinline__ void mma16816(float* d, const uint32_t* a,
                                         uint32_t b0, uint32_t b1) {
    asm volatile("mma.sync.aligned.m16n8k16.row.col.f32.f16.f16.f32 "
        "{%0,%1,%2,%3},{%4,%5,%6,%7},{%8,%9},{%0,%1,%2,%3};"
        : "+f"(d[0]), "+f"(d[1]), "+f"(d[2]), "+f"(d[3])
        : "r"(a[0]), "r"(a[1]), "r"(a[2]), "r"(a[3]), "r"(b0), "r"(b1));
}

#define CPA16(dst, src) \
    asm volatile("cp.async.cg.shared.global [%0], [%1], 16;" :: "r"(dst), "l"(src))
#define CPA_COMMIT() asm volatile("cp.async.commit_group;" ::: "memory")
#define CPA_WAIT(n)  asm volatile("cp.async.wait_group %0;" :: "n"(n) : "memory")

// ---------------- K0: zero stat accumulators (graph-replay safe) ------------
__global__ __launch_bounds__(256) void init_kernel() {
    int i = blockIdx.x * 256 + threadIdx.x;
    if (i < BH * 64 * 64) g_G[i] = 0.f;
    if (i < BH * 64)      g_ksum[i] = 0.f;
    if (i < BH)           g_kmax2[i] = 0.f;
}

// ---------------- K1: std over H (axis=-2 of [B,L,H,E]) + tanh, fp16 out ---
__global__ __launch_bounds__(256) void transform_kernel(
    const float* __restrict__ qg, const float* __restrict__ kg,
    const float* __restrict__ dw, const float* __restrict__ dp)
{
    const int NPT = Bsz * Ll * Ee;
    int gid = blockIdx.x * blockDim.x + threadIdx.x;
    int which = (gid >= NPT) ? 1 : 0;
    int id = gid - which * NPT;
    const float* x  = which ? kg   : qg;
    __half*      xt = which ? g_kt : g_qt;

    int e  = id & 63;
    int bl = id >> 6;
    int b  = bl >> 11, l = bl & 2047;

    const float* base = x + ((size_t)bl * Hh) * Ee + e;
    float v[Hh];
    float s1 = 0.f;
    #pragma unroll
    for (int h = 0; h < Hh; h++) { v[h] = base[h * Ee]; s1 += v[h]; }
    float mean = s1 * (1.f / Hh);
    float s2 = 0.f;
    #pragma unroll
    for (int h = 0; h < Hh; h++) { float d = v[h] - mean; s2 += d * d; }
    float stdv = sqrtf(s2 * (1.f / (Hh - 1)));
    float sc = (1.f / (stdv + EPSF)) * dw[0];
    float p  = dp[0];

    size_t obase = (((size_t)b * Hh) * Ll + l) * Ee + e;
    #pragma unroll
    for (int h = 0; h < Hh; h++)
        xt[obase + (size_t)h * Ll * Ee] = __float2half(tanhf(v[h] * sc) * p);
}

// ---------------- K1b: V transpose to [bh][e][s], fp16 ----------------------
__global__ __launch_bounds__(256) void vtrans_kernel(const float* __restrict__ v)
{
    __shared__ float tile[64][65];
    int bh = blockIdx.y;
    int b = bh >> 3, h = bh & 7;
    int s0 = blockIdx.x << 6;
    int t = threadIdx.x;
    int e = t & 63, sr = t >> 6;
    const float* vb = v + ((size_t)b * Ss * Hh + h) * Ee;
    #pragma unroll
    for (int i = 0; i < 16; i++) {
        int s = sr + i * 4;
        tile[s][e] = vb[(size_t)(s0 + s) * (Hh * Ee) + e];
    }
    __syncthreads();
    int sp = t & 63, er = t >> 6;
    __half* ob = g_vt + (size_t)bh * Ee * Ss;
    #pragma unroll
    for (int i = 0; i < 16; i++) {
        int e2 = er + i * 4;
        ob[(size_t)e2 * Ss + s0 + sp] = __float2half(tile[sp][e2]);
    }
}

// ---------------- K2: Gram G = K^T K, ksum, max row norm --------------------
// grid (16 s-chunks of 128, BH), 256 thr. Convert once to fp32 smem, then
// float4 LDS + pure-FFMA inner loop.
__global__ __launch_bounds__(256) void gram_kernel()
{
    __shared__ float fs[128 * 64];      // 32 KB
    __shared__ float red[4 * 64];
    __shared__ float redmax[8];

    int t = threadIdx.x, lane = t & 31;
    int bh = blockIdx.y, s0 = blockIdx.x << 7;
    int tx = t & 15, ty = t >> 4;
    int e = t & 63, q4 = t >> 6;

    // load 128x64 halves, convert once to fp32 smem
    const uint4* kb = (const uint4*)(g_kt + ((size_t)bh * Ss + s0) * Ee);
    #pragma unroll
    for (int i = 0; i < 4; i++) {
        int idx = t + i * 256;                    // uint4 index (8 halves)
        uint4 u = kb[idx];
        const __half2* hp = (const __half2*)&u;
        float* dst = fs + idx * 8;
        float2 f0 = __half22float2(hp[0]);
        float2 f1 = __half22float2(hp[1]);
        float2 f2 = __half22float2(hp[2]);
        float2 f3 = __half22float2(hp[3]);
        *(float4*)(dst)     = make_float4(f0.x, f0.y, f1.x, f1.y);
        *(float4*)(dst + 4) = make_float4(f2.x, f2.y, f3.x, f3.y);
    }
    __syncthreads();

    float acc[4][4] = {};
    for (int s = 0; s < 128; s++) {
        float4 av = *(const float4*)&fs[s * 64 + ty * 4];
        float4 bv = *(const float4*)&fs[s * 64 + tx * 4];
        float a[4] = {av.x, av.y, av.z, av.w};
        float bb[4] = {bv.x, bv.y, bv.z, bv.w};
        #pragma unroll
        for (int i = 0; i < 4; i++)
            #pragma unroll
            for (int j = 0; j < 4; j++)
                acc[i][j] += a[i] * bb[j];
    }
    float psum = 0.f, pmax = 0.f;
    #pragma unroll
    for (int s4 = 0; s4 < 32; s4++) psum += fs[(q4 + s4 * 4) * 64 + e];
    if (t < 128) {
        float n2 = 0.f;
        const float4* rp = (const float4*)(fs + t * 64);
        #pragma unroll
        for (int i = 0; i < 16; i++) {
            float4 f = rp[i];
            n2 += f.x * f.x + f.y * f.y + f.z * f.z + f.w * f.w;
        }
        pmax = n2;
    }

    #pragma unroll
    for (int i = 0; i < 4; i++)
        #pragma unroll
        for (int j = 0; j < 4; j++)
            atomicAdd(&g_G[bh * 4096 + (ty * 4 + i) * 64 + tx * 4 + j], acc[i][j]);

    red[q4 * 64 + e] = psum;
    #pragma unroll
    for (int off = 16; off; off >>= 1)
        pmax = fmaxf(pmax, __shfl_xor_sync(0xffffffffu, pmax, off));
    if (lane == 0) redmax[t >> 5] = pmax;
    __syncthreads();
    if (t < 64)
        atomicAdd(&g_ksum[bh * 64 + t], red[t] + red[64 + t] + red[128 + t] + red[192 + t]);
    if (t == 0) {
        float m = 0.f;
        #pragma unroll
        for (int w = 0; w < 8; w++) m = fmaxf(m, redmax[w]);
        atomicMax((int*)&g_kmax2[bh], __float_as_int(m));   // all values >= 0
    }
}

// ---------------- K3: single-pass flash attention, fused stats prologue -----
// grid (Ll/128, BH), 256 thr = 8 warps, 16 L-rows/warp. Dynamic smem 72 KB:
// K[2][128*72]h | V[2][64*136]h | c[128]f | m[128]f.
// Stats (c = scale/tau, m = ||q||*max||k||) computed in the prologue using G
// staged into the V buffer-1 region (dead until tile-1 prefetch).
#define KBUF 18432
#define VBUF 17408

__device__ __forceinline__ void load_k_tile(uint32_t kdst, const uint4* ksrc, int t) {
    #pragma unroll
    for (int i = 0; i < 4; i++) {
        int idx = t + i * 256;
        uint32_t dst = kdst + (uint32_t)((idx >> 3) * 72 + (idx & 7) * 8) * 2;
        CPA16(dst, ksrc + idx);
    }
}
__device__ __forceinline__ void load_v_tile(uint32_t vdst, const uint4* vsrc, int st, int t) {
    #pragma unroll
    for (int i = 0; i < 4; i++) {
        int idx = t + i * 256;
        int e = idx >> 4, seg = idx & 15;
        uint32_t dst = vdst + (uint32_t)(e * 136 + seg * 8) * 2;
        CPA16(dst, vsrc + e * 256 + st * 16 + seg);
    }
}

__global__ __launch_bounds__(256) void attn_kernel(float* __restrict__ out)
{
    extern __shared__ __align__(16) char dyn[];
    __half* Ksm = (__half*)dyn;
    __half* Vsm = (__half*)(dyn + 2 * KBUF);
    float*  csm = (float*)(dyn + 2 * KBUF + 2 * VBUF);
    float*  msm = csm + 128;
    // V buffer-1 region doubles as fp32 G + ksum + kmax staging for the prologue
    float*  Gs   = (float*)(dyn + 2 * KBUF + VBUF);    // 64*64 floats = 16384 B
    float*  ksm2 = Gs + 4096;                          // 64 floats + kmax at [64]

    int t = threadIdx.x, lane = t & 31, wid = t >> 5;
    int bh = blockIdx.y, l0 = blockIdx.x << 7;
    int b = bh >> 3, h = bh & 7;
    int wrow = wid * 16;
    int g = lane >> 2, tig = lane & 3;

    uint32_t ksb = smem_u32(Ksm), vsb = smem_u32(Vsm);

    const uint4* kbase = (const uint4*)(g_kt + (size_t)bh * Ss * Ee);
    const uint4* vbase = (const uint4*)(g_vt + (size_t)bh * Ee * Ss);

    // prefetch tile 0 into buffer 0 (async) while we stage Q + G
    load_k_tile(ksb, kbase, t);
    load_v_tile(vsb, vbase, 0, t);
    CPA_COMMIT();

    {   // stage Q into K buffer 1
        const uint4* qsrc = (const uint4*)(g_qt + ((size_t)bh * Ll + l0) * Ee);
        #pragma unroll
        for (int i = 0; i < 4; i++) {
            int idx = t + i * 256;
            *(uint4*)&Ksm[KBUF / 2 + (idx >> 3) * 72 + (idx & 7) * 8] = qsrc[idx];
        }
    }
    {   // stage G (fp32) + ksum + kmax into V buffer 1 region
        const float4* gsrc = (const float4*)(g_G + bh * 4096);
        #pragma unroll
        for (int i = 0; i < 4; i++)
            ((float4*)Gs)[t + i * 256] = gsrc[t + i * 256];
        if (t < 64) ksm2[t] = g_ksum[bh * 64 + t];
        if (t == 0) ksm2[64] = g_kmax2[bh];
    }
    __syncthreads();

    // resident Q A-fragments
    uint32_t aq[4][4];
    {
        int r  = wrow + ((lane >> 3) & 1) * 8 + (lane & 7);
        int cb = ((lane >> 4) & 1) * 8;
        #pragma unroll
        for (int kk = 0; kk < 4; kk++) {
            uint32_t addr = ksb + KBUF + (uint32_t)(r * 72 + kk * 16 + cb) * 2;
            LDMX4(aq[kk][0], aq[kk][1], aq[kk][2], aq[kk][3], addr);
        }
    }

    // ---- fused stats: tmp = Q*G (G symmetric -> row-major float4 reads) ----
    {
        const __half* Qs1 = Ksm + KBUF / 2;
        int tx = t & 15, ty = t >> 4;
        float kmax = sqrtf(ksm2[64]);
        #pragma unroll
        for (int pass = 0; pass < 2; pass++) {
            int rbase = pass * 64 + ty * 4;
            float acc[4][4] = {};
            for (int k = 0; k < 64; k++) {
                float a[4];
                #pragma unroll
                for (int i = 0; i < 4; i++) a[i] = __half2float(Qs1[(rbase + i) * 72 + k]);
                float4 bv = *(const float4*)&Gs[k * 64 + tx * 4];
                #pragma unroll
                for (int i = 0; i < 4; i++) {
                    acc[i][0] += a[i] * bv.x; acc[i][1] += a[i] * bv.y;
                    acc[i][2] += a[i] * bv.z; acc[i][3] += a[i] * bv.w;
                }
            }
            #pragma unroll
            for (int i = 0; i < 4; i++) {
                float qv[4];
                #pragma unroll
                for (int j = 0; j < 4; j++)
                    qv[j] = __half2float(Qs1[(rbase + i) * 72 + tx * 4 + j]);
                float psq  = acc[i][0]*qv[0] + acc[i][1]*qv[1] + acc[i][2]*qv[2] + acc[i][3]*qv[3];
                float psum = qv[0]*ksm2[tx*4] + qv[1]*ksm2[tx*4+1]
                           + qv[2]*ksm2[tx*4+2] + qv[3]*ksm2[tx*4+3];
                float pnrm = qv[0]*qv[0] + qv[1]*qv[1] + qv[2]*qv[2] + qv[3]*qv[3];
                #pragma unroll
                for (int off = 1; off <= 8; off <<= 1) {
                    psq  += __shfl_xor_sync(0xffffffffu, psq,  off);
                    psum += __shfl_xor_sync(0xffffffffu, psum, off);
                    pnrm += __shfl_xor_sync(0xffffffffu, pnrm, off);
                }
                if (tx == 0) {
                    float mean = psum / (float)Ss;
                    float var  = fmaxf((psq - psum * mean) / (float)(Ss - 1), 0.f);
                    csm[rbase + i] = SCALE / sqrtf(var + EPSF);
                    msm[rbase + i] = sqrtf(pnrm) * kmax;     // upper bound on row max
                }
            }
        }
    }
    __syncthreads();   // stats written; Q/G buffers free for tile-1 prefetch

    float c_lo = csm[wrow + g],     m_lo = msm[wrow + g];
    float c_hi = csm[wrow + g + 8], m_hi = msm[wrow + g + 8];

    float oacc[8][4];
    #pragma unroll
    for (int i = 0; i < 8; i++)
        oacc[i][0] = oacc[i][1] = oacc[i][2] = oacc[i][3] = 0.f;
    float den_lo = 0.f, den_hi = 0.f;

    for (int st = 0; st < 16; st++) {
        if (st < 15) {
            uint32_t nb = (uint32_t)((st + 1) & 1);
            load_k_tile(ksb + nb * KBUF, kbase + (st + 1) * 1024, t);
            load_v_tile(vsb + nb * VBUF, vbase, st + 1, t);
            CPA_COMMIT();
            CPA_WAIT(1);
        } else {
            CPA_WAIT(0);
        }
        __syncthreads();

        uint32_t kb2 = ksb + (uint32_t)(st & 1) * KBUF;
        uint32_t vb2 = vsb + (uint32_t)(st & 1) * VBUF;

        uint32_t ap[8][4];
        #pragma unroll
        for (int j = 0; j < 16; j++) {
            float acc[4] = {0.f, 0.f, 0.f, 0.f};
            uint32_t addr = kb2 + (uint32_t)((j * 8 + (lane & 7)) * 72 + (lane >> 3) * 8) * 2;
            uint32_t b0, b1, b2, b3, b4, b5, b6, b7;
            LDMX4(b0, b1, b2, b3, addr);
            LDMX4(b4, b5, b6, b7, addr + 64);
            mma16816(acc, aq[0], b0, b1);
            mma16816(acc, aq[1], b2, b3);
            mma16816(acc, aq[2], b4, b5);
            mma16816(acc, aq[3], b6, b7);
            float e0 = __expf(c_lo * (acc[0] - m_lo));
            float e1 = __expf(c_lo * (acc[1] - m_lo));
            float e2 = __expf(c_hi * (acc[2] - m_hi));
            float e3 = __expf(c_hi * (acc[3] - m_hi));
            den_lo += e0 + e1;
            den_hi += e2 + e3;
            __half2 p01 = __floats2half2_rn(e0, e1);
            __half2 p23 = __floats2half2_rn(e2, e3);
            ap[j >> 1][(j & 1) * 2 + 0] = *(uint32_t*)&p01;
            ap[j >> 1][(j & 1) * 2 + 1] = *(uint32_t*)&p23;
        }
        #pragma unroll
        for (int kpp = 0; kpp < 4; kpp++) {
            #pragma unroll
            for (int dn = 0; dn < 8; dn++) {
                uint32_t addr = vb2 +
                    (uint32_t)((dn * 8 + (lane & 7)) * 136 + kpp * 32 + (lane >> 3) * 8) * 2;
                uint32_t b0, b1, b2, b3;
                LDMX4(b0, b1, b2, b3, addr);
                mma16816(oacc[dn], ap[2 * kpp],     b0, b1);
                mma16816(oacc[dn], ap[2 * kpp + 1], b2, b3);
            }
        }
        __syncthreads();
    }
    #pragma unroll
    for (int off = 1; off <= 2; off <<= 1) {
        den_lo += __shfl_xor_sync(0xffffffffu, den_lo, off);
        den_hi += __shfl_xor_sync(0xffffffffu, den_hi, off);
    }
    float inv_lo = 1.f / den_lo, inv_hi = 1.f / den_hi;
    int row_lo = l0 + wrow + g, row_hi = row_lo + 8;
    float* plo = out + (((size_t)b * Ll + row_lo) * Hh + h) * Ee;
    float* phi = out + (((size_t)b * Ll + row_hi) * Hh + h) * Ee;
    #pragma unroll
    for (int dn = 0; dn < 8; dn++) {
        int d = dn * 8 + tig * 2;
        *(float2*)&plo[d] = make_float2(oacc[dn][0] * inv_lo, oacc[dn][1] * inv_lo);
        *(float2*)&phi[d] = make_float2(oacc[dn][2] * inv_hi, oacc[dn][3] * inv_hi);
    }
}

// ---------------- launch ----------------------------------------------------
extern "C" void kernel_launch(void* const* d_in, const int* in_sizes, int n_in,
                              void* d_out, int out_size)
{
    const float* q  = (const float*)d_in[0];
    const float* k  = (const float*)d_in[1];
    const float* v  = (const float*)d_in[2];
    // d_in[3] attn_mask: unused (mask_flag=False)
    const float* dw = (const float*)d_in[4];
    const float* dp = (const float*)d_in[5];
    float* out = (float*)d_out;

    const int ATTN_SMEM = 2 * KBUF + 2 * VBUF + 2 * 128 * 4;   // 72704 B
    cudaFuncSetAttribute(attn_kernel, cudaFuncAttributeMaxDynamicSharedMemorySize, ATTN_SMEM);

    init_kernel<<<(BH * 64 * 64 + 255) / 256, 256>>>();
    transform_kernel<<<4096, 256>>>(q, k, dw, dp);
    vtrans_kernel<<<dim3(Ss / 64, BH), 256>>>(v);
    gram_kernel<<<dim3(16, BH), 256>>>();
    attn_kernel<<<dim3(Ll / 128, BH), 256, ATTN_SMEM>>>(out);
}